// round 3
// baseline (speedup 1.0000x reference)
#include <cuda_runtime.h>
#include <math.h>

// Problem constants (fixed shapes per reference)
#define SEGS 65536
#define NPTS 16777216

// ---------------- scratch (device globals; no allocation allowed) ----------
__device__ unsigned int g_umin[SEGS * 3];   // encoded float min
__device__ unsigned int g_umax[SEGS * 3];   // encoded float max
__device__ float4       g_sumcnt[SEGS];     // {sum.x, sum.y, sum.z, count}
__device__ float4       g_stats[SEGS];      // {mean.x, mean.y, mean.z, 1/(diam+0.01)}

// Monotonic float<->uint encoding: unsigned compare order == float order
__device__ __forceinline__ unsigned int enc(float f) {
    unsigned int u = __float_as_uint(f);
    return (u & 0x80000000u) ? ~u : (u | 0x80000000u);
}
__device__ __forceinline__ float dec(unsigned int u) {
    return __uint_as_float((u & 0x80000000u) ? (u & 0x7FFFFFFFu) : ~u);
}

// ---------------- pass 1: reset accumulators -------------------------------
__global__ void k_init() {
    int t = blockIdx.x * blockDim.x + threadIdx.x;
    if (t < SEGS * 3) {
        g_umin[t] = 0xFFFFFFFFu;   // >= enc of anything
        g_umax[t] = 0u;            // <= enc of anything
    }
    if (t < SEGS) g_sumcnt[t] = make_float4(0.f, 0.f, 0.f, 0.f);
}

// ---------------- pass 2: scatter min/max/sum/count ------------------------
// 7 atomic instructions per point:
//   6x scalar RED.MIN/MAX.U32 (monotone-encoded float min/max)
//   1x RED.ADD.V4.F32 packing {x, y, z, 1.0} (sum + count fused)
__device__ __forceinline__ void scatter_one(int s, float x, float y, float z) {
    unsigned int ex = enc(x), ey = enc(y), ez = enc(z);
    int b = 3 * s;
    atomicMin(&g_umin[b + 0], ex);
    atomicMin(&g_umin[b + 1], ey);
    atomicMin(&g_umin[b + 2], ez);
    atomicMax(&g_umax[b + 0], ex);
    atomicMax(&g_umax[b + 1], ey);
    atomicMax(&g_umax[b + 2], ez);
    asm volatile("red.global.add.v4.f32 [%0], {%1, %2, %3, %4};"
                 :: "l"(&g_sumcnt[s]), "f"(x), "f"(y), "f"(z), "f"(1.0f)
                 : "memory");
}

// Each thread handles 4 points: 3x float4 pos loads + 1x int4 idx load.
__global__ __launch_bounds__(256, 8)
void k_scatter4(const float4* __restrict__ pos4,
                const int4* __restrict__ idx4, int nq) {
    int stride = gridDim.x * blockDim.x;
    for (int q = blockIdx.x * blockDim.x + threadIdx.x; q < nq; q += stride) {
        float4 a = pos4[3 * q + 0];   // p0.xyz p1.x
        float4 b = pos4[3 * q + 1];   // p1.yz  p2.xy
        float4 c = pos4[3 * q + 2];   // p2.z   p3.xyz
        int4 s = idx4[q];
        scatter_one(s.x, a.x, a.y, a.z);
        scatter_one(s.y, a.w, b.x, b.y);
        scatter_one(s.z, b.z, b.w, c.x);
        scatter_one(s.w, c.y, c.z, c.w);
    }
}

// ---------------- pass 3: finalize per-segment stats -----------------------
__global__ void k_finalize(float* __restrict__ diam_out) {
    int s = blockIdx.x * blockDim.x + threadIdx.x;
    if (s >= SEGS) return;
    float4 sc = g_sumcnt[s];
    float cnt = sc.w;
    float diam, mx_, my_, mz_;
    if (cnt > 0.0f) {
        float inv_c = 1.0f / fmaxf(cnt, 1.0f);
        mx_ = sc.x * inv_c;
        my_ = sc.y * inv_c;
        mz_ = sc.z * inv_c;
        float dx = dec(g_umax[3 * s + 0]) - dec(g_umin[3 * s + 0]);
        float dy = dec(g_umax[3 * s + 1]) - dec(g_umin[3 * s + 1]);
        float dz = dec(g_umax[3 * s + 2]) - dec(g_umin[3 * s + 2]);
        diam = fmaxf(dx, fmaxf(dy, dz));
    } else {
        // jax identity fills: min=+inf, max=-inf -> diam = -inf; sum=0 -> mean=0
        mx_ = my_ = mz_ = 0.0f;
        diam = -INFINITY;
    }
    diam_out[s] = diam;
    float4 st;
    st.x = mx_; st.y = my_; st.z = mz_;
    st.w = 1.0f / (diam + 0.01f);
    g_stats[s] = st;
}

// ---------------- pass 4: gather + normalize -------------------------------
// Each thread handles 4 points: 3x float4 in, 3x float4 out, 1x int4 idx.
__global__ __launch_bounds__(256, 8)
void k_normalize4(const float4* __restrict__ pos4,
                  const int4* __restrict__ idx4,
                  float4* __restrict__ out4, int nq) {
    int stride = gridDim.x * blockDim.x;
    for (int q = blockIdx.x * blockDim.x + threadIdx.x; q < nq; q += stride) {
        float4 a = pos4[3 * q + 0];
        float4 b = pos4[3 * q + 1];
        float4 c = pos4[3 * q + 2];
        int4 s = idx4[q];
        float4 s0 = __ldg(&g_stats[s.x]);   // 1MB table, L2-resident
        float4 s1 = __ldg(&g_stats[s.y]);
        float4 s2 = __ldg(&g_stats[s.z]);
        float4 s3 = __ldg(&g_stats[s.w]);
        float4 o0, o1, o2;
        o0.x = (a.x - s0.x) * s0.w;
        o0.y = (a.y - s0.y) * s0.w;
        o0.z = (a.z - s0.z) * s0.w;
        o0.w = (a.w - s1.x) * s1.w;
        o1.x = (b.x - s1.y) * s1.w;
        o1.y = (b.y - s1.z) * s1.w;
        o1.z = (b.z - s2.x) * s2.w;
        o1.w = (b.w - s2.y) * s2.w;
        o2.x = (c.x - s2.z) * s2.w;
        o2.y = (c.y - s3.x) * s3.w;
        o2.z = (c.z - s3.y) * s3.w;
        o2.w = (c.w - s3.z) * s3.w;
        out4[3 * q + 0] = o0;
        out4[3 * q + 1] = o1;
        out4[3 * q + 2] = o2;
    }
}

// ---------------- launch ----------------------------------------------------
extern "C" void kernel_launch(void* const* d_in, const int* in_sizes, int n_in,
                              void* d_out, int out_size) {
    const float* pos = (const float*)d_in[0];
    const int*   idx = (const int*)d_in[1];
    int n = in_sizes[1];               // point count from idx length (16777216)

    float* out  = (float*)d_out;       // [N*3] normalized points
    float* diam = out + (size_t)n * 3; // [S] diameters follow

    const int T = 256;
    int nq = n / 4;                    // N is a multiple of 4
    int grid_sc = (nq + T - 1) / T;
    if (grid_sc > 148 * 32) grid_sc = 148 * 32;

    k_init<<<(SEGS * 3 + T - 1) / T, T>>>();
    k_scatter4<<<grid_sc, T>>>((const float4*)pos, (const int4*)idx, nq);
    k_finalize<<<(SEGS + T - 1) / T, T>>>(diam);
    k_normalize4<<<grid_sc, T>>>((const float4*)pos, (const int4*)idx,
                                 (float4*)out, nq);
}